// round 1
// baseline (speedup 1.0000x reference)
#include <cuda_runtime.h>
#include <math.h>

#define NN 4096
#define BM 128
#define BN 128
#define BK 16
#define TM 8
#define TN 8

// 64 MB scratch for the similarity / attention matrix (device global: no allocs).
__device__ float g_S[(size_t)NN * NN];

// NT GEMM: C[i][j] = scale * sum_k A[i][k] * B[j][k]
// A: [NN, NN] row-major, B: [NN, NN] row-major, C: [NN, NN] row-major.
__global__ __launch_bounds__(256) void gemm_nt(const float* __restrict__ A,
                                               const float* __restrict__ B,
                                               float* __restrict__ C,
                                               float scale) {
    __shared__ float As[BK][BM];
    __shared__ float Bs[BK][BN];

    const int tid = threadIdx.x;
    const int tx = tid % (BN / TN);  // 0..15 (n direction)
    const int ty = tid / (BN / TN);  // 0..15 (m direction)
    const int rowBase = blockIdx.y * BM;
    const int colBase = blockIdx.x * BN;

    float acc[TM][TN];
#pragma unroll
    for (int i = 0; i < TM; i++)
#pragma unroll
        for (int j = 0; j < TN; j++) acc[i][j] = 0.f;

    for (int kt = 0; kt < NN; kt += BK) {
        // Load 128x16 tiles of A and B (512 float4 each; 2 per thread),
        // storing k-major into shared for broadcast-friendly reads.
#pragma unroll
        for (int l = 0; l < 2; l++) {
            int f = tid + l * 256;   // float4 index within tile
            int m = f >> 2;          // row within tile (0..127)
            int k4 = (f & 3) * 4;    // k offset (0,4,8,12)
            float4 va = *reinterpret_cast<const float4*>(
                &A[(size_t)(rowBase + m) * NN + kt + k4]);
            As[k4 + 0][m] = va.x;
            As[k4 + 1][m] = va.y;
            As[k4 + 2][m] = va.z;
            As[k4 + 3][m] = va.w;
            float4 vb = *reinterpret_cast<const float4*>(
                &B[(size_t)(colBase + m) * NN + kt + k4]);
            Bs[k4 + 0][m] = vb.x;
            Bs[k4 + 1][m] = vb.y;
            Bs[k4 + 2][m] = vb.z;
            Bs[k4 + 3][m] = vb.w;
        }
        __syncthreads();

#pragma unroll
        for (int k = 0; k < BK; k++) {
            float a[TM], b[TN];
            // 32B-aligned vector reads from shared
            float4 a0 = *reinterpret_cast<const float4*>(&As[k][ty * TM]);
            float4 a1 = *reinterpret_cast<const float4*>(&As[k][ty * TM + 4]);
            float4 b0 = *reinterpret_cast<const float4*>(&Bs[k][tx * TN]);
            float4 b1 = *reinterpret_cast<const float4*>(&Bs[k][tx * TN + 4]);
            a[0] = a0.x; a[1] = a0.y; a[2] = a0.z; a[3] = a0.w;
            a[4] = a1.x; a[5] = a1.y; a[6] = a1.z; a[7] = a1.w;
            b[0] = b0.x; b[1] = b0.y; b[2] = b0.z; b[3] = b0.w;
            b[4] = b1.x; b[5] = b1.y; b[6] = b1.z; b[7] = b1.w;
#pragma unroll
            for (int i = 0; i < TM; i++)
#pragma unroll
                for (int j = 0; j < TN; j++)
                    acc[i][j] = fmaf(a[i], b[j], acc[i][j]);
        }
        __syncthreads();
    }

#pragma unroll
    for (int i = 0; i < TM; i++) {
        size_t r = (size_t)(rowBase + ty * TM + i) * NN + colBase + tx * TN;
#pragma unroll
        for (int j = 0; j < TN; j += 4) {
            float4 v;
            v.x = acc[i][j + 0] * scale;
            v.y = acc[i][j + 1] * scale;
            v.z = acc[i][j + 2] * scale;
            v.w = acc[i][j + 3] * scale;
            *reinterpret_cast<float4*>(&C[r + j]) = v;
        }
    }
}

// Row softmax with masked diagonal: P[i][i] = 0, P[i][j] = exp(s_ij - m_i)/Z_i.
__global__ __launch_bounds__(256) void softmax_rows(float* __restrict__ S) {
    const int row = blockIdx.x;
    float* r = S + (size_t)row * NN;
    __shared__ float red[256];
    const int t = threadIdx.x;

    // 1) row max over j != row
    float m = -3.4e38f;
    for (int j = t; j < NN; j += 256) {
        float v = r[j];
        if (j != row) m = fmaxf(m, v);
    }
    red[t] = m;
    __syncthreads();
    for (int s = 128; s > 0; s >>= 1) {
        if (t < s) red[t] = fmaxf(red[t], red[t + s]);
        __syncthreads();
    }
    m = red[0];
    __syncthreads();

    // 2) row sum of exp
    float sum = 0.f;
    for (int j = t; j < NN; j += 256) {
        if (j != row) sum += __expf(r[j] - m);
    }
    red[t] = sum;
    __syncthreads();
    for (int s = 128; s > 0; s >>= 1) {
        if (t < s) red[t] += red[t + s];
        __syncthreads();
    }
    const float inv = 1.f / red[0];

    // 3) normalize in place
    for (int j = t; j < NN; j += 256) {
        r[j] = (j == row) ? 0.f : __expf(r[j] - m) * inv;
    }
}

extern "C" void kernel_launch(void* const* d_in, const int* in_sizes, int n_in,
                              void* d_out, int out_size) {
    const float* feats = (const float*)d_in[0];
    float* out = (float*)d_out;

    void* sp = nullptr;
    cudaGetSymbolAddress(&sp, g_S);
    float* S = (float*)sp;

    dim3 grid(NN / BN, NN / BM);
    dim3 block(256);

    // S = feats @ feats^T / D   (== x @ x^T with x = feats/sqrt(D))
    gemm_nt<<<grid, block>>>(feats, feats, S, 1.0f / (float)NN);
    // P = softmax(S) with diagonal masked
    softmax_rows<<<NN, 256>>>(S);
    // out = P @ feats^T / sqrt(D)  (== attn @ x^T)
    gemm_nt<<<grid, block>>>(S, feats, out, 1.0f / 64.0f);
}

// round 3
// speedup vs baseline: 3.2508x; 3.2508x over previous
#include <cuda_runtime.h>
#include <stdint.h>

#define NN 4096
#define BM 128
#define BN 128
#define BK 16
#define KT (NN / BK)
#define STAGES 3
#define THREADS 256
#define LDSTR 20  // BK + 4 floats pad: conflict-free fragment loads

// 64 MB scratch matrices (device globals: no allocations).
__device__ float g_S[(size_t)NN * NN];  // logits / attention probs
__device__ float g_F[(size_t)NN * NN];  // tf32-rounded feats

__device__ __forceinline__ uint32_t smem_u32(const void* p) {
    uint32_t a;
    asm("{ .reg .u64 t; cvta.to.shared.u64 t, %1; cvt.u32.u64 %0, t; }" : "=r"(a) : "l"(p));
    return a;
}
__device__ __forceinline__ float to_tf32(float x) {
    float y;
    asm("cvt.rna.tf32.f32 %0, %1;" : "=f"(y) : "f"(x));
    return y;
}

#define CP_ASYNC16(dst, src) \
    asm volatile("cp.async.cg.shared.global [%0], [%1], 16;" :: "r"(dst), "l"(src) : "memory")
#define CP_COMMIT() asm volatile("cp.async.commit_group;" ::: "memory")
#define CP_WAIT(n) asm volatile("cp.async.wait_group %0;" ::"n"(n) : "memory")

// D += A*B, tf32 inputs (b32 regs), fp32 accum
#define MMA_TF32(d, a, b)                                                        \
    asm volatile(                                                                \
        "mma.sync.aligned.m16n8k8.row.col.f32.tf32.tf32.f32 "                    \
        "{%0,%1,%2,%3}, {%4,%5,%6,%7}, {%8,%9}, {%0,%1,%2,%3};"                  \
        : "+f"((d)[0]), "+f"((d)[1]), "+f"((d)[2]), "+f"((d)[3])                 \
        : "r"((a)[0]), "r"((a)[1]), "r"((a)[2]), "r"((a)[3]),                    \
          "r"((b)[0]), "r"((b)[1]))

// NT GEMM: C[i][j] = scale * sum_k A[i][k]*B[j][k]; A,B row-major [NN,NN].
__global__ __launch_bounds__(THREADS, 2) void gemm_nt_mma(const float* __restrict__ A,
                                                          const float* __restrict__ B,
                                                          float* __restrict__ C,
                                                          float scale) {
    extern __shared__ float smem[];
    float* As = smem;                            // STAGES * BM * LDSTR
    float* Bs = smem + STAGES * BM * LDSTR;      // STAGES * BN * LDSTR

    const int tid = threadIdx.x;
    const int wid = tid >> 5;
    const int lane = tid & 31;
    const int q = lane >> 2;   // 0..7
    const int r = lane & 3;    // 0..3
    const int wm = wid & 1;    // warp m: 0..1  (64 rows each)
    const int wn = wid >> 1;   // warp n: 0..3  (32 cols each)
    const int rowBase = blockIdx.y * BM;
    const int colBase = blockIdx.x * BN;

    // per-thread gmem load coords: 512 float4 per tile, 2 per thread per operand
    const int ldRow0 = tid >> 2;         // 0..63
    const int ldC4 = (tid & 3) * 4;      // k offset 0,4,8,12

    float c[4][4][4];
#pragma unroll
    for (int i = 0; i < 4; i++)
#pragma unroll
        for (int j = 0; j < 4; j++)
#pragma unroll
            for (int e = 0; e < 4; e++) c[i][j][e] = 0.f;

    const uint32_t asb = smem_u32(As);
    const uint32_t bsb = smem_u32(Bs);

    // ---- pipeline load helper (stage s, k-tile kt) ----
#define LOAD_STAGE(s, kt)                                                          \
    do {                                                                           \
        const uint32_t a_s = asb + (s) * (BM * LDSTR * 4);                         \
        const uint32_t b_s = bsb + (s) * (BN * LDSTR * 4);                         \
        const float* Ag = A + (size_t)rowBase * NN + (size_t)(kt) * BK;            \
        const float* Bg = B + (size_t)colBase * NN + (size_t)(kt) * BK;            \
        _Pragma("unroll") for (int l = 0; l < 2; l++) {                            \
            int row = ldRow0 + l * 64;                                             \
            CP_ASYNC16(a_s + (row * LDSTR + ldC4) * 4,                             \
                       Ag + (size_t)row * NN + ldC4);                              \
            CP_ASYNC16(b_s + (row * LDSTR + ldC4) * 4,                             \
                       Bg + (size_t)row * NN + ldC4);                              \
        }                                                                          \
        CP_COMMIT();                                                               \
    } while (0)

    LOAD_STAGE(0, 0);
    LOAD_STAGE(1, 1);

    for (int kt = 0; kt < KT; kt++) {
        CP_WAIT(1);
        __syncthreads();

        if (kt + 2 < KT) {
            LOAD_STAGE((kt + 2) % STAGES, kt + 2);
        } else {
            CP_COMMIT();  // keep group counting aligned
        }

        const float* as = As + (kt % STAGES) * BM * LDSTR + (wm * 64) * LDSTR;
        const float* bs = Bs + (kt % STAGES) * BN * LDSTR + (wn * 32) * LDSTR;

#pragma unroll
        for (int k0 = 0; k0 < 2; k0++) {  // two k=8 steps cover BK=16
            uint32_t a[4][4], b[4][2];
#pragma unroll
            for (int im = 0; im < 4; im++) {
                const float* p = as + (im * 16 + q) * LDSTR + k0 * 8 + r;
                a[im][0] = __float_as_uint(p[0]);
                a[im][1] = __float_as_uint(p[8 * LDSTR]);
                a[im][2] = __float_as_uint(p[4]);
                a[im][3] = __float_as_uint(p[8 * LDSTR + 4]);
            }
#pragma unroll
            for (int in_ = 0; in_ < 4; in_++) {
                const float* p = bs + (in_ * 8 + q) * LDSTR + k0 * 8 + r;
                b[in_][0] = __float_as_uint(p[0]);
                b[in_][1] = __float_as_uint(p[4]);
            }
#pragma unroll
            for (int im = 0; im < 4; im++)
#pragma unroll
                for (int in_ = 0; in_ < 4; in_++) MMA_TF32(c[im][in_], a[im], b[in_]);
        }
        __syncthreads();
    }

    // ---- epilogue: scale + store ----
#pragma unroll
    for (int im = 0; im < 4; im++) {
        const int row0 = rowBase + wm * 64 + im * 16 + q;
#pragma unroll
        for (int in_ = 0; in_ < 4; in_++) {
            const int col = colBase + wn * 32 + in_ * 8 + 2 * r;
            float2 v0 = make_float2(c[im][in_][0] * scale, c[im][in_][1] * scale);
            float2 v1 = make_float2(c[im][in_][2] * scale, c[im][in_][3] * scale);
            *reinterpret_cast<float2*>(C + (size_t)row0 * NN + col) = v0;
            *reinterpret_cast<float2*>(C + (size_t)(row0 + 8) * NN + col) = v1;
        }
    }
}

// ---------------- round feats to tf32 (RN) once ----------------
__global__ __launch_bounds__(256) void round_tf32_kernel(const float* __restrict__ in,
                                                         float* __restrict__ out) {
    size_t i = ((size_t)blockIdx.x * 256 + threadIdx.x) * 4;
    float4 v = *reinterpret_cast<const float4*>(in + i);
    v.x = to_tf32(v.x);
    v.y = to_tf32(v.y);
    v.z = to_tf32(v.z);
    v.w = to_tf32(v.w);
    *reinterpret_cast<float4*>(out + i) = v;
}

// ---------------- row softmax, diagonal masked; writes tf32-rounded probs ----------------
__global__ __launch_bounds__(256) void softmax_rows(float* __restrict__ S) {
    const int row = blockIdx.x;
    float* r = S + (size_t)row * NN;
    __shared__ float red[256];
    const int t = threadIdx.x;

    float m = -3.4e38f;
    for (int j = t; j < NN; j += 256) {
        float v = r[j];
        if (j != row) m = fmaxf(m, v);
    }
    red[t] = m;
    __syncthreads();
    for (int s = 128; s > 0; s >>= 1) {
        if (t < s) red[t] = fmaxf(red[t], red[t + s]);
        __syncthreads();
    }
    m = red[0];
    __syncthreads();

    float sum = 0.f;
    for (int j = t; j < NN; j += 256) {
        if (j != row) sum += __expf(r[j] - m);
    }
    red[t] = sum;
    __syncthreads();
    for (int s = 128; s > 0; s >>= 1) {
        if (t < s) red[t] += red[t + s];
        __syncthreads();
    }
    const float inv = 1.f / red[0];

    for (int j = t; j < NN; j += 256) {
        r[j] = (j == row) ? 0.f : to_tf32(__expf(r[j] - m) * inv);
    }
}

extern "C" void kernel_launch(void* const* d_in, const int* in_sizes, int n_in,
                              void* d_out, int out_size) {
    const float* feats = (const float*)d_in[0];
    float* out = (float*)d_out;

    void* sp = nullptr;
    void* fp = nullptr;
    cudaGetSymbolAddress(&sp, g_S);
    cudaGetSymbolAddress(&fp, g_F);
    float* S = (float*)sp;
    float* F = (float*)fp;

    const int smemBytes = STAGES * (BM + BN) * LDSTR * 4;  // 61440
    cudaFuncSetAttribute(gemm_nt_mma, cudaFuncAttributeMaxDynamicSharedMemorySize, smemBytes);

    // 1) RN-round feats to tf32 (HW truncation inside MMA is then exact)
    round_tf32_kernel<<<(NN * NN) / 1024, 256>>>(feats, F);

    dim3 grid(NN / BN, NN / BM);  // (32, 32)
    // 2) S = F @ F^T / D
    gemm_nt_mma<<<grid, THREADS, smemBytes>>>(F, F, S, 1.0f / (float)NN);
    // 3) P = softmax(S), diagonal masked, tf32-rounded
    softmax_rows<<<NN, 256>>>(S);
    // 4) out = P @ F^T / sqrt(D)
    gemm_nt_mma<<<grid, THREADS, smemBytes>>>(S, F, out, 1.0f / 64.0f);
}

// round 4
// speedup vs baseline: 4.5649x; 1.4042x over previous
#include <cuda_runtime.h>
#include <cuda_bf16.h>
#include <stdint.h>

#define NN 4096
#define THREADS 256
#define STAGES 3
#define KT32 (NN / 32)

// tf32 GEMM tile
#define BM 128
#define BN 128
#define LDSTR 36    // floats; bank = (q*4 + r) -> conflict-free
// bf16 GEMM tile
#define LDSTRB 40   // halves; 80B row stride -> conflict-free

// Scratch (device globals: no allocations).
__device__ float g_S[(size_t)NN * NN];            // logits / probs (64 MB)
__device__ float g_F[(size_t)NN * NN];            // tf32-rounded feats (64 MB)
__device__ __nv_bfloat16 g_Fb[(size_t)NN * NN];   // bf16 feats (32 MB)

__device__ __forceinline__ uint32_t smem_u32(const void* p) {
    uint32_t a;
    asm("{ .reg .u64 t; cvta.to.shared.u64 t, %1; cvt.u32.u64 %0, t; }" : "=r"(a) : "l"(p));
    return a;
}
__device__ __forceinline__ float to_tf32(float x) {
    float y;
    asm("cvt.rna.tf32.f32 %0, %1;" : "=f"(y) : "f"(x));
    return y;
}

#define CP_ASYNC16(dst, src) \
    asm volatile("cp.async.cg.shared.global [%0], [%1], 16;" :: "r"(dst), "l"(src) : "memory")
#define CP_COMMIT() asm volatile("cp.async.commit_group;" ::: "memory")
#define CP_WAIT(n) asm volatile("cp.async.wait_group %0;" ::"n"(n) : "memory")

#define MMA_TF32(d, a, b)                                                        \
    asm volatile(                                                                \
        "mma.sync.aligned.m16n8k8.row.col.f32.tf32.tf32.f32 "                    \
        "{%0,%1,%2,%3}, {%4,%5,%6,%7}, {%8,%9}, {%0,%1,%2,%3};"                  \
        : "+f"((d)[0]), "+f"((d)[1]), "+f"((d)[2]), "+f"((d)[3])                 \
        : "r"((a)[0]), "r"((a)[1]), "r"((a)[2]), "r"((a)[3]),                    \
          "r"((b)[0]), "r"((b)[1]))

#define MMA_BF16(d, a, b)                                                        \
    asm volatile(                                                                \
        "mma.sync.aligned.m16n8k16.row.col.f32.bf16.bf16.f32 "                   \
        "{%0,%1,%2,%3}, {%4,%5,%6,%7}, {%8,%9}, {%0,%1,%2,%3};"                  \
        : "+f"((d)[0]), "+f"((d)[1]), "+f"((d)[2]), "+f"((d)[3])                 \
        : "r"((a)[0]), "r"((a)[1]), "r"((a)[2]), "r"((a)[3]),                    \
          "r"((b)[0]), "r"((b)[1]))

// ======================= GEMM1: bf16 NT, S = Fb @ Fb^T * scale =======================
// stage bytes: A tile 128x32 bf16, row stride 80B -> 10240; B same.
#define ASTG_B (BM * LDSTRB * 2)
#define SMEM1_STAGE (2 * ASTG_B)
#define SMEM1_TOTAL (STAGES * SMEM1_STAGE)

__global__ __launch_bounds__(THREADS, 2) void gemm_nt_bf16(const __nv_bfloat16* __restrict__ A,
                                                           const __nv_bfloat16* __restrict__ B,
                                                           float* __restrict__ C, float scale) {
    extern __shared__ char smem[];
    const uint32_t sb = smem_u32(smem);
    const int tid = threadIdx.x;
    const int wid = tid >> 5;
    const int lane = tid & 31;
    const int q = lane >> 2, r = lane & 3;
    const int wm = wid & 1, wn = wid >> 1;
    const int rowBase = blockIdx.y * BM;
    const int colBase = blockIdx.x * BN;

    // loads: 128 rows x 4 chunks(16B) per tile; 2 chunks/thread/tile
    const int ldRow = tid >> 2;       // 0..63 (+64)
    const int ldC = (tid & 3) * 16;   // byte offset in row (0..48)

    float c[4][4][4];
#pragma unroll
    for (int i = 0; i < 4; i++)
#pragma unroll
        for (int j = 0; j < 4; j++)
#pragma unroll
            for (int e = 0; e < 4; e++) c[i][j][e] = 0.f;

#define LOAD1(s, kt)                                                               \
    do {                                                                           \
        const uint32_t a_s = sb + (s) * SMEM1_STAGE;                               \
        const uint32_t b_s = a_s + ASTG_B;                                         \
        const __nv_bfloat16* Ag = A + (size_t)rowBase * NN + (size_t)(kt) * 32;    \
        const __nv_bfloat16* Bg = B + (size_t)colBase * NN + (size_t)(kt) * 32;    \
        _Pragma("unroll") for (int l = 0; l < 2; l++) {                            \
            int row = ldRow + l * 64;                                              \
            CP_ASYNC16(a_s + row * 80 + ldC, (const char*)Ag + (size_t)row * (NN * 2) + ldC); \
            CP_ASYNC16(b_s + row * 80 + ldC, (const char*)Bg + (size_t)row * (NN * 2) + ldC); \
        }                                                                          \
        CP_COMMIT();                                                               \
    } while (0)

    LOAD1(0, 0);
    LOAD1(1, 1);

    for (int kt = 0; kt < KT32; kt++) {
        CP_WAIT(1);
        __syncthreads();
        if (kt + 2 < KT32) LOAD1((kt + 2) % STAGES, kt + 2);
        else CP_COMMIT();

        const char* as = smem + (kt % STAGES) * SMEM1_STAGE + (wm * 64) * 80;
        const char* bs = smem + (kt % STAGES) * SMEM1_STAGE + ASTG_B + (wn * 32) * 80;

#pragma unroll
        for (int ks = 0; ks < 2; ks++) {  // two k=16 steps cover 32
            uint32_t a[4][4], b[4][2];
#pragma unroll
            for (int im = 0; im < 4; im++) {
                const char* p = as + (im * 16 + q) * 80 + ks * 32 + r * 4;
                a[im][0] = *(const uint32_t*)(p);
                a[im][1] = *(const uint32_t*)(p + 8 * 80);
                a[im][2] = *(const uint32_t*)(p + 16);
                a[im][3] = *(const uint32_t*)(p + 8 * 80 + 16);
            }
#pragma unroll
            for (int in_ = 0; in_ < 4; in_++) {
                const char* p = bs + (in_ * 8 + q) * 80 + ks * 32 + r * 4;
                b[in_][0] = *(const uint32_t*)(p);
                b[in_][1] = *(const uint32_t*)(p + 16);
            }
#pragma unroll
            for (int im = 0; im < 4; im++)
#pragma unroll
                for (int in_ = 0; in_ < 4; in_++) MMA_BF16(c[im][in_], a[im], b[in_]);
        }
        __syncthreads();
    }

#pragma unroll
    for (int im = 0; im < 4; im++) {
        const int row0 = rowBase + wm * 64 + im * 16 + q;
#pragma unroll
        for (int in_ = 0; in_ < 4; in_++) {
            const int col = colBase + wn * 32 + in_ * 8 + 2 * r;
            float2 v0 = make_float2(c[im][in_][0] * scale, c[im][in_][1] * scale);
            float2 v1 = make_float2(c[im][in_][2] * scale, c[im][in_][3] * scale);
            *reinterpret_cast<float2*>(C + (size_t)row0 * NN + col) = v0;
            *reinterpret_cast<float2*>(C + (size_t)(row0 + 8) * NN + col) = v1;
        }
    }
}

// ======================= GEMM2: tf32 NT, out = P @ F^T * scale =======================
#define ASTG_F (BM * LDSTR * 4)          // 18432
#define SMEM2_STAGE (2 * ASTG_F)         // 36864
#define SMEM2_TOTAL (STAGES * SMEM2_STAGE)

__global__ __launch_bounds__(THREADS, 2) void gemm_nt_tf32(const float* __restrict__ A,
                                                           const float* __restrict__ B,
                                                           float* __restrict__ C, float scale) {
    extern __shared__ char smemc[];
    float* smem = (float*)smemc;
    const uint32_t sb = smem_u32(smem);
    const int tid = threadIdx.x;
    const int wid = tid >> 5;
    const int lane = tid & 31;
    const int q = lane >> 2, r = lane & 3;
    const int wm = wid & 1, wn = wid >> 1;
    const int rowBase = blockIdx.y * BM;
    const int colBase = blockIdx.x * BN;

    // loads: 128 rows x 8 chunks(16B) per tile; 4 chunks/thread/tile
    const int ldRow = tid >> 3;          // 0..31 (+32,64,96)
    const int ldC4 = (tid & 7) * 4;      // float offset

    float c[4][4][4];
#pragma unroll
    for (int i = 0; i < 4; i++)
#pragma unroll
        for (int j = 0; j < 4; j++)
#pragma unroll
            for (int e = 0; e < 4; e++) c[i][j][e] = 0.f;

#define LOAD2(s, kt)                                                               \
    do {                                                                           \
        const uint32_t a_s = sb + (s) * SMEM2_STAGE;                               \
        const uint32_t b_s = a_s + ASTG_F;                                         \
        const float* Ag = A + (size_t)rowBase * NN + (size_t)(kt) * 32;            \
        const float* Bg = B + (size_t)colBase * NN + (size_t)(kt) * 32;            \
        _Pragma("unroll") for (int l = 0; l < 4; l++) {                            \
            int row = ldRow + l * 32;                                              \
            CP_ASYNC16(a_s + (row * LDSTR + ldC4) * 4, Ag + (size_t)row * NN + ldC4); \
            CP_ASYNC16(b_s + (row * LDSTR + ldC4) * 4, Bg + (size_t)row * NN + ldC4); \
        }                                                                          \
        CP_COMMIT();                                                               \
    } while (0)

    LOAD2(0, 0);
    LOAD2(1, 1);

    for (int kt = 0; kt < KT32; kt++) {
        CP_WAIT(1);
        __syncthreads();
        if (kt + 2 < KT32) LOAD2((kt + 2) % STAGES, kt + 2);
        else CP_COMMIT();

        const float* as = smem + (kt % STAGES) * (SMEM2_STAGE / 4) + (wm * 64) * LDSTR;
        const float* bs = smem + (kt % STAGES) * (SMEM2_STAGE / 4) + (ASTG_F / 4) + (wn * 32) * LDSTR;

#pragma unroll
        for (int k0 = 0; k0 < 4; k0++) {  // four k=8 steps cover 32
            uint32_t a[4][4], b[4][2];
#pragma unroll
            for (int im = 0; im < 4; im++) {
                const float* p = as + (im * 16 + q) * LDSTR + k0 * 8 + r;
                a[im][0] = __float_as_uint(p[0]);
                a[im][1] = __float_as_uint(p[8 * LDSTR]);
                a[im][2] = __float_as_uint(p[4]);
                a[im][3] = __float_as_uint(p[8 * LDSTR + 4]);
            }
#pragma unroll
            for (int in_ = 0; in_ < 4; in_++) {
                const float* p = bs + (in_ * 8 + q) * LDSTR + k0 * 8 + r;
                b[in_][0] = __float_as_uint(p[0]);
                b[in_][1] = __float_as_uint(p[4]);
            }
#pragma unroll
            for (int im = 0; im < 4; im++)
#pragma unroll
                for (int in_ = 0; in_ < 4; in_++) MMA_TF32(c[im][in_], a[im], b[in_]);
        }
        __syncthreads();
    }

#pragma unroll
    for (int im = 0; im < 4; im++) {
        const int row0 = rowBase + wm * 64 + im * 16 + q;
#pragma unroll
        for (int in_ = 0; in_ < 4; in_++) {
            const int col = colBase + wn * 32 + in_ * 8 + 2 * r;
            float2 v0 = make_float2(c[im][in_][0] * scale, c[im][in_][1] * scale);
            float2 v1 = make_float2(c[im][in_][2] * scale, c[im][in_][3] * scale);
            *reinterpret_cast<float2*>(C + (size_t)row0 * NN + col) = v0;
            *reinterpret_cast<float2*>(C + (size_t)(row0 + 8) * NN + col) = v1;
        }
    }
}

// ---------------- prep: tf32-round + bf16-convert feats ----------------
__global__ __launch_bounds__(256) void prep_feats(const float* __restrict__ in,
                                                  float* __restrict__ f32t,
                                                  __nv_bfloat16* __restrict__ b16) {
    size_t i = ((size_t)blockIdx.x * 256 + threadIdx.x) * 4;
    float4 v = *reinterpret_cast<const float4*>(in + i);
    float4 t;
    t.x = to_tf32(v.x);
    t.y = to_tf32(v.y);
    t.z = to_tf32(v.z);
    t.w = to_tf32(v.w);
    *reinterpret_cast<float4*>(f32t + i) = t;
    __nv_bfloat162 b0 = __floats2bfloat162_rn(v.x, v.y);
    __nv_bfloat162 b1 = __floats2bfloat162_rn(v.z, v.w);
    *reinterpret_cast<__nv_bfloat162*>(b16 + i) = b0;
    *reinterpret_cast<__nv_bfloat162*>(b16 + i + 2) = b1;
}

// ---------------- row softmax, diag masked; writes tf32-rounded probs ----------------
__global__ __launch_bounds__(256) void softmax_rows(float* __restrict__ S) {
    const int row = blockIdx.x;
    float* r = S + (size_t)row * NN;
    __shared__ float red[256];
    const int t = threadIdx.x;

    float m = -3.4e38f;
    for (int j = t; j < NN; j += 256) {
        float v = r[j];
        if (j != row) m = fmaxf(m, v);
    }
    red[t] = m;
    __syncthreads();
    for (int s = 128; s > 0; s >>= 1) {
        if (t < s) red[t] = fmaxf(red[t], red[t + s]);
        __syncthreads();
    }
    m = red[0];
    __syncthreads();

    float sum = 0.f;
    for (int j = t; j < NN; j += 256) {
        if (j != row) sum += __expf(r[j] - m);
    }
    red[t] = sum;
    __syncthreads();
    for (int s = 128; s > 0; s >>= 1) {
        if (t < s) red[t] += red[t + s];
        __syncthreads();
    }
    const float inv = 1.f / red[0];

    for (int j = t; j < NN; j += 256) {
        r[j] = (j == row) ? 0.f : to_tf32(__expf(r[j] - m) * inv);
    }
}

extern "C" void kernel_launch(void* const* d_in, const int* in_sizes, int n_in,
                              void* d_out, int out_size) {
    const float* feats = (const float*)d_in[0];
    float* out = (float*)d_out;

    void *sp, *fp, *bp;
    cudaGetSymbolAddress(&sp, g_S);
    cudaGetSymbolAddress(&fp, g_F);
    cudaGetSymbolAddress(&bp, g_Fb);
    float* S = (float*)sp;
    float* F = (float*)fp;
    __nv_bfloat16* Fb = (__nv_bfloat16*)bp;

    cudaFuncSetAttribute(gemm_nt_bf16, cudaFuncAttributeMaxDynamicSharedMemorySize, SMEM1_TOTAL);
    cudaFuncSetAttribute(gemm_nt_tf32, cudaFuncAttributeMaxDynamicSharedMemorySize, SMEM2_TOTAL);

    prep_feats<<<(NN * NN) / 1024, 256>>>(feats, F, Fb);

    dim3 grid(NN / BN, NN / BM);  // (32, 32)
    // S = Fb @ Fb^T / D   (bf16 tensor, fp32 accum; logit error ~2e-5 abs)
    gemm_nt_bf16<<<grid, THREADS, SMEM1_TOTAL>>>(Fb, Fb, S, 1.0f / (float)NN);
    // P = softmax(S) with masked diagonal, tf32-rounded
    softmax_rows<<<NN, 256>>>(S);
    // out = P @ F^T / sqrt(D)  (tf32 tensor)
    gemm_nt_tf32<<<grid, THREADS, SMEM2_TOTAL>>>(S, F, out, 1.0f / 64.0f);
}

// round 5
// speedup vs baseline: 6.2193x; 1.3624x over previous
#include <cuda_runtime.h>
#include <cuda_fp16.h>
#include <stdint.h>

#define NN 4096
#define THREADS 256
#define STAGES 3
#define KT32 (NN / 32)
#define BM 128
#define BN 128
#define LDB 80  // bytes per smem row: 32 halves (64B) + 16B pad -> conflict-free ldmatrix

#define ASTG (BM * LDB)             // 10240 bytes per A stage
#define STG (2 * ASTG)              // 20480 per stage (A+B)
#define SMEM_TOTAL (STAGES * STG)   // 61440

// Scratch (device globals: no allocations).
__device__ float g_S[(size_t)NN * NN];          // fp32 logits (64 MB)
__device__ __half g_Fh[(size_t)NN * NN];        // f16 feats (32 MB)
__device__ __half g_Ph[(size_t)NN * NN];        // f16 probs (32 MB)

__device__ __forceinline__ uint32_t smem_u32(const void* p) {
    uint32_t a;
    asm("{ .reg .u64 t; cvta.to.shared.u64 t, %1; cvt.u32.u64 %0, t; }" : "=r"(a) : "l"(p));
    return a;
}

#define CP_ASYNC16(dst, src) \
    asm volatile("cp.async.cg.shared.global [%0], [%1], 16;" :: "r"(dst), "l"(src) : "memory")
#define CP_COMMIT() asm volatile("cp.async.commit_group;" ::: "memory")
#define CP_WAIT(n) asm volatile("cp.async.wait_group %0;" ::"n"(n) : "memory")

#define LDSM_X4(r0, r1, r2, r3, addr)                                        \
    asm volatile("ldmatrix.sync.aligned.m8n8.x4.shared.b16 {%0,%1,%2,%3}, [%4];" \
                 : "=r"(r0), "=r"(r1), "=r"(r2), "=r"(r3) : "r"(addr))

#define MMA_F16(d, a, b0, b1)                                                \
    asm volatile(                                                            \
        "mma.sync.aligned.m16n8k16.row.col.f32.f16.f16.f32 "                 \
        "{%0,%1,%2,%3}, {%4,%5,%6,%7}, {%8,%9}, {%0,%1,%2,%3};"              \
        : "+f"((d)[0]), "+f"((d)[1]), "+f"((d)[2]), "+f"((d)[3])             \
        : "r"((a)[0]), "r"((a)[1]), "r"((a)[2]), "r"((a)[3]),                \
          "r"(b0), "r"(b1))

// NT GEMM, f16 inputs, fp32 accum: C[i][j] = scale * sum_k A[i][k]*B[j][k]
__global__ __launch_bounds__(THREADS, 2) void gemm_nt_f16(const __half* __restrict__ A,
                                                          const __half* __restrict__ B,
                                                          float* __restrict__ C, float scale) {
    extern __shared__ char smem[];
    const uint32_t sb = smem_u32(smem);
    const int tid = threadIdx.x;
    const int wid = tid >> 5;
    const int lane = tid & 31;
    const int q = lane >> 2, r = lane & 3;
    const int wm = wid & 1;   // 2 warp rows x 64
    const int wn = wid >> 1;  // 4 warp cols x 32
    const int rowBase = blockIdx.y * BM;
    const int colBase = blockIdx.x * BN;

    // cp.async coords: 128 rows x 64B per operand tile; 4 chunks/row; 2 chunks/thread
    const int ldRow = tid >> 2;
    const int ldC = (tid & 3) * 16;

    // ldmatrix lane mapping: matrix ml = lane>>3; row-in-group = lane&7
    const int ml = lane >> 3;
    const int lrow = (ml & 1) * 8 + (lane & 7);
    const int lk = (ml >> 1) * 16;  // byte offset: matrices 2,3 take k+8 halves

    float c[4][4][4];
#pragma unroll
    for (int i = 0; i < 4; i++)
#pragma unroll
        for (int j = 0; j < 4; j++)
#pragma unroll
            for (int e = 0; e < 4; e++) c[i][j][e] = 0.f;

#define LOADK(s, kt)                                                               \
    do {                                                                           \
        const uint32_t a_s = sb + (s) * STG;                                       \
        const uint32_t b_s = a_s + ASTG;                                           \
        const char* Ag = (const char*)(A + (size_t)rowBase * NN + (size_t)(kt) * 32); \
        const char* Bg = (const char*)(B + (size_t)colBase * NN + (size_t)(kt) * 32); \
        _Pragma("unroll") for (int l = 0; l < 2; l++) {                            \
            int row = ldRow + l * 64;                                              \
            CP_ASYNC16(a_s + row * LDB + ldC, Ag + (size_t)row * (NN * 2) + ldC);  \
            CP_ASYNC16(b_s + row * LDB + ldC, Bg + (size_t)row * (NN * 2) + ldC);  \
        }                                                                          \
        CP_COMMIT();                                                               \
    } while (0)

    LOADK(0, 0);
    LOADK(1, 1);

    for (int kt = 0; kt < KT32; kt++) {
        CP_WAIT(1);
        __syncthreads();
        if (kt + 2 < KT32) LOADK((kt + 2) % STAGES, kt + 2);
        else CP_COMMIT();

        const uint32_t a_s = sb + (kt % STAGES) * STG;
        const uint32_t b_s = a_s + ASTG;
        const uint32_t abase = a_s + (wm * 64 + lrow) * LDB + lk;
        const uint32_t bbase = b_s + (wn * 32 + lrow) * LDB + lk;

#pragma unroll
        for (int ks = 0; ks < 2; ks++) {  // two k=16 steps cover BK=32
            uint32_t a[4][4], b[2][4];
#pragma unroll
            for (int im = 0; im < 4; im++)
                LDSM_X4(a[im][0], a[im][1], a[im][2], a[im][3],
                        abase + im * (16 * LDB) + ks * 32);
#pragma unroll
            for (int jn = 0; jn < 2; jn++)
                LDSM_X4(b[jn][0], b[jn][1], b[jn][2], b[jn][3],
                        bbase + jn * (16 * LDB) + ks * 32);
            // b[jn][0]=b0(n-tile 2jn), b[jn][1]=b0(2jn+1), b[jn][2]=b1(2jn), b[jn][3]=b1(2jn+1)
#pragma unroll
            for (int im = 0; im < 4; im++)
#pragma unroll
                for (int in_ = 0; in_ < 4; in_++) {
                    const int jn = in_ >> 1, o = in_ & 1;
                    MMA_F16(c[im][in_], a[im], b[jn][o], b[jn][2 + o]);
                }
        }
        __syncthreads();
    }

    // epilogue: c0,c1 -> (row q, col 2r..2r+1); c2,c3 -> (row q+8)
#pragma unroll
    for (int im = 0; im < 4; im++) {
        const int row0 = rowBase + wm * 64 + im * 16 + q;
#pragma unroll
        for (int in_ = 0; in_ < 4; in_++) {
            const int col = colBase + wn * 32 + in_ * 8 + 2 * r;
            float2 v0 = make_float2(c[im][in_][0] * scale, c[im][in_][1] * scale);
            float2 v1 = make_float2(c[im][in_][2] * scale, c[im][in_][3] * scale);
            *reinterpret_cast<float2*>(C + (size_t)row0 * NN + col) = v0;
            *reinterpret_cast<float2*>(C + (size_t)(row0 + 8) * NN + col) = v1;
        }
    }
}

// ---------------- prep: feats f32 -> f16 ----------------
__global__ __launch_bounds__(256) void prep_feats(const float* __restrict__ in,
                                                  __half* __restrict__ out) {
    size_t i = ((size_t)blockIdx.x * 256 + threadIdx.x) * 8;
    float4 v0 = *reinterpret_cast<const float4*>(in + i);
    float4 v1 = *reinterpret_cast<const float4*>(in + i + 4);
    __half2 h[4];
    h[0] = __floats2half2_rn(v0.x, v0.y);
    h[1] = __floats2half2_rn(v0.z, v0.w);
    h[2] = __floats2half2_rn(v1.x, v1.y);
    h[3] = __floats2half2_rn(v1.z, v1.w);
    *reinterpret_cast<uint4*>(out + i) = *reinterpret_cast<uint4*>(h);
}

// ---------------- row softmax, diag masked, smem-cached row, f16 output ----------------
__global__ __launch_bounds__(256) void softmax_rows(const float* __restrict__ S,
                                                    __half* __restrict__ P) {
    __shared__ float row[NN];  // 16 KB
    __shared__ float red[256];
    const int ri = blockIdx.x;
    const int t = threadIdx.x;
    const float4* src = reinterpret_cast<const float4*>(S + (size_t)ri * NN);

    for (int j = t; j < NN / 4; j += 256) reinterpret_cast<float4*>(row)[j] = src[j];
    __syncthreads();
    if (t == 0) row[ri] = -3.4e38f;  // mask diagonal
    __syncthreads();

    float m = -3.4e38f;
    for (int j = t; j < NN; j += 256) m = fmaxf(m, row[j]);
    red[t] = m;
    __syncthreads();
    for (int s = 128; s > 0; s >>= 1) {
        if (t < s) red[t] = fmaxf(red[t], red[t + s]);
        __syncthreads();
    }
    m = red[0];
    __syncthreads();

    float sum = 0.f;
    for (int j = t; j < NN; j += 256) {
        float e = __expf(row[j] - m);  // diag -> exp(-huge) = 0
        row[j] = e;
        sum += e;
    }
    red[t] = sum;
    __syncthreads();
    for (int s = 128; s > 0; s >>= 1) {
        if (t < s) red[t] += red[t + s];
        __syncthreads();
    }
    const float inv = 1.f / red[0];
    __syncthreads();

    __half2* dst = reinterpret_cast<__half2*>(P + (size_t)ri * NN);
    for (int j = t; j < NN / 2; j += 256)
        dst[j] = __floats2half2_rn(row[2 * j] * inv, row[2 * j + 1] * inv);
}

extern "C" void kernel_launch(void* const* d_in, const int* in_sizes, int n_in,
                              void* d_out, int out_size) {
    const float* feats = (const float*)d_in[0];
    float* out = (float*)d_out;

    void *sp, *fp, *pp;
    cudaGetSymbolAddress(&sp, g_S);
    cudaGetSymbolAddress(&fp, g_Fh);
    cudaGetSymbolAddress(&pp, g_Ph);
    float* S = (float*)sp;
    __half* Fh = (__half*)fp;
    __half* Ph = (__half*)pp;

    cudaFuncSetAttribute(gemm_nt_f16, cudaFuncAttributeMaxDynamicSharedMemorySize, SMEM_TOTAL);

    prep_feats<<<(NN * NN) / 2048, 256>>>(feats, Fh);

    dim3 grid(NN / BN, NN / BM);  // (32, 32)
    // S = Fh @ Fh^T / D   (f16 mma, fp32 accum)
    gemm_nt_f16<<<grid, THREADS, SMEM_TOTAL>>>(Fh, Fh, S, 1.0f / (float)NN);
    // P = softmax(S), diagonal masked, f16
    softmax_rows<<<NN, 256>>>(S, Ph);
    // out = P @ Fh^T / sqrt(D)   (f16 mma, fp32 accum)
    gemm_nt_f16<<<grid, THREADS, SMEM_TOTAL>>>(Ph, Fh, out, 1.0f / 64.0f);
}

// round 6
// speedup vs baseline: 6.9363x; 1.1153x over previous
#include <cuda_runtime.h>
#include <cuda_fp16.h>
#include <stdint.h>

#define NN 4096
#define THREADS 256
#define STAGES 3
#define BK 64
#define KT (NN / BK)   // 64 iterations
#define BM 128
#define BN 128
#define LDB 144  // bytes per smem row: 64 halves (128B) + 16B pad -> conflict-free ldmatrix

#define ASTG (BM * LDB)             // 18432 bytes per operand stage
#define STG (2 * ASTG)              // 36864 per stage (A+B)
#define SMEM_TOTAL (STAGES * STG)   // 110592

// Scratch (device globals: no allocations).
__device__ float g_S[(size_t)NN * NN];          // fp32 logits (64 MB)
__device__ __half g_Fh[(size_t)NN * NN];        // f16 feats (32 MB)
__device__ __half g_Ph[(size_t)NN * NN];        // f16 probs (32 MB)

__device__ __forceinline__ uint32_t smem_u32(const void* p) {
    uint32_t a;
    asm("{ .reg .u64 t; cvta.to.shared.u64 t, %1; cvt.u32.u64 %0, t; }" : "=r"(a) : "l"(p));
    return a;
}

#define CP_ASYNC16(dst, src) \
    asm volatile("cp.async.cg.shared.global [%0], [%1], 16;" :: "r"(dst), "l"(src) : "memory")
#define CP_COMMIT() asm volatile("cp.async.commit_group;" ::: "memory")
#define CP_WAIT(n) asm volatile("cp.async.wait_group %0;" ::"n"(n) : "memory")

#define LDSM_X4(r0, r1, r2, r3, addr)                                        \
    asm volatile("ldmatrix.sync.aligned.m8n8.x4.shared.b16 {%0,%1,%2,%3}, [%4];" \
                 : "=r"(r0), "=r"(r1), "=r"(r2), "=r"(r3) : "r"(addr))

#define MMA_F16(d, a, b0, b1)                                                \
    asm volatile(                                                            \
        "mma.sync.aligned.m16n8k16.row.col.f32.f16.f16.f32 "                 \
        "{%0,%1,%2,%3}, {%4,%5,%6,%7}, {%8,%9}, {%0,%1,%2,%3};"              \
        : "+f"((d)[0]), "+f"((d)[1]), "+f"((d)[2]), "+f"((d)[3])             \
        : "r"((a)[0]), "r"((a)[1]), "r"((a)[2]), "r"((a)[3]),                \
          "r"(b0), "r"(b1))

// NT GEMM, f16 inputs, fp32 accum: C[i][j] = scale * sum_k A[i][k]*B[j][k]
__global__ __launch_bounds__(THREADS, 2) void gemm_nt_f16(const __half* __restrict__ A,
                                                          const __half* __restrict__ B,
                                                          float* __restrict__ C, float scale) {
    extern __shared__ char smem[];
    const uint32_t sb = smem_u32(smem);
    const int tid = threadIdx.x;
    const int wid = tid >> 5;
    const int lane = tid & 31;
    const int q = lane >> 2, r = lane & 3;
    const int wm = wid & 1;   // 2 warp rows x 64
    const int wn = wid >> 1;  // 4 warp cols x 32
    const int rowBase = blockIdx.y * BM;
    const int colBase = blockIdx.x * BN;

    // cp.async coords: per operand tile 128 rows x 128B -> 8 chunks(16B)/row,
    // thread t handles rows (t>>3)+{0,32,64,96}, chunk (t&7)
    const int ldRow = tid >> 3;
    const int ldC = (tid & 7) * 16;

    // ldmatrix lane mapping
    const int ml = lane >> 3;
    const int lrow = (ml & 1) * 8 + (lane & 7);
    const int lk = (ml >> 1) * 16;

    float c[4][4][4];
#pragma unroll
    for (int i = 0; i < 4; i++)
#pragma unroll
        for (int j = 0; j < 4; j++)
#pragma unroll
            for (int e = 0; e < 4; e++) c[i][j][e] = 0.f;

#define LOADK(s, kt)                                                               \
    do {                                                                           \
        const uint32_t a_s = sb + (s) * STG;                                       \
        const uint32_t b_s = a_s + ASTG;                                           \
        const char* Ag = (const char*)(A + (size_t)rowBase * NN + (size_t)(kt) * BK); \
        const char* Bg = (const char*)(B + (size_t)colBase * NN + (size_t)(kt) * BK); \
        _Pragma("unroll") for (int l = 0; l < 4; l++) {                            \
            int row = ldRow + l * 32;                                              \
            CP_ASYNC16(a_s + row * LDB + ldC, Ag + (size_t)row * (NN * 2) + ldC);  \
            CP_ASYNC16(b_s + row * LDB + ldC, Bg + (size_t)row * (NN * 2) + ldC);  \
        }                                                                          \
        CP_COMMIT();                                                               \
    } while (0)

    LOADK(0, 0);
    LOADK(1, 1);

    for (int kt = 0; kt < KT; kt++) {
        CP_WAIT(1);
        __syncthreads();  // all warps done with iter kt-1 reads; stage (kt-1)%3 free
        if (kt + 2 < KT) LOADK((kt + 2) % STAGES, kt + 2);
        else CP_COMMIT();

        const uint32_t a_s = sb + (kt % STAGES) * STG;
        const uint32_t abase = a_s + (wm * 64 + lrow) * LDB + lk;
        const uint32_t bbase = a_s + ASTG + (wn * 32 + lrow) * LDB + lk;

#pragma unroll
        for (int ks = 0; ks < 4; ks++) {  // four k=16 steps cover BK=64
            uint32_t a[4][4], b[2][4];
#pragma unroll
            for (int im = 0; im < 4; im++)
                LDSM_X4(a[im][0], a[im][1], a[im][2], a[im][3],
                        abase + im * (16 * LDB) + ks * 32);
#pragma unroll
            for (int jn = 0; jn < 2; jn++)
                LDSM_X4(b[jn][0], b[jn][1], b[jn][2], b[jn][3],
                        bbase + jn * (16 * LDB) + ks * 32);
#pragma unroll
            for (int im = 0; im < 4; im++)
#pragma unroll
                for (int in_ = 0; in_ < 4; in_++) {
                    const int jn = in_ >> 1, o = in_ & 1;
                    MMA_F16(c[im][in_], a[im], b[jn][o], b[jn][2 + o]);
                }
        }
        // no trailing sync: next iteration's barrier protects stage reuse
    }

#pragma unroll
    for (int im = 0; im < 4; im++) {
        const int row0 = rowBase + wm * 64 + im * 16 + q;
#pragma unroll
        for (int in_ = 0; in_ < 4; in_++) {
            const int col = colBase + wn * 32 + in_ * 8 + 2 * r;
            float2 v0 = make_float2(c[im][in_][0] * scale, c[im][in_][1] * scale);
            float2 v1 = make_float2(c[im][in_][2] * scale, c[im][in_][3] * scale);
            *reinterpret_cast<float2*>(C + (size_t)row0 * NN + col) = v0;
            *reinterpret_cast<float2*>(C + (size_t)(row0 + 8) * NN + col) = v1;
        }
    }
}

// ---------------- prep: feats f32 -> f16 ----------------
__global__ __launch_bounds__(256) void prep_feats(const float* __restrict__ in,
                                                  __half* __restrict__ out) {
    size_t i = ((size_t)blockIdx.x * 256 + threadIdx.x) * 8;
    float4 v0 = *reinterpret_cast<const float4*>(in + i);
    float4 v1 = *reinterpret_cast<const float4*>(in + i + 4);
    __half2 h[4];
    h[0] = __floats2half2_rn(v0.x, v0.y);
    h[1] = __floats2half2_rn(v0.z, v0.w);
    h[2] = __floats2half2_rn(v1.x, v1.y);
    h[3] = __floats2half2_rn(v1.z, v1.w);
    *reinterpret_cast<uint4*>(out + i) = *reinterpret_cast<uint4*>(h);
}

// ---------------- row softmax, diag masked, smem-cached row, f16 output ----------------
__global__ __launch_bounds__(256) void softmax_rows(const float* __restrict__ S,
                                                    __half* __restrict__ P) {
    __shared__ float row[NN];  // 16 KB
    __shared__ float red[256];
    const int ri = blockIdx.x;
    const int t = threadIdx.x;
    const float4* src = reinterpret_cast<const float4*>(S + (size_t)ri * NN);

    for (int j = t; j < NN / 4; j += 256) reinterpret_cast<float4*>(row)[j] = src[j];
    __syncthreads();
    if (t == 0) row[ri] = -3.4e38f;  // mask diagonal
    __syncthreads();

    float m = -3.4e38f;
    for (int j = t; j < NN; j += 256) m = fmaxf(m, row[j]);
    red[t] = m;
    __syncthreads();
    for (int s = 128; s > 0; s >>= 1) {
        if (t < s) red[t] = fmaxf(red[t], red[t + s]);
        __syncthreads();
    }
    m = red[0];
    __syncthreads();

    float sum = 0.f;
    for (int j = t; j < NN; j += 256) {
        float e = __expf(row[j] - m);  // diag -> exp(-huge) = 0
        row[j] = e;
        sum += e;
    }
    red[t] = sum;
    __syncthreads();
    for (int s = 128; s > 0; s >>= 1) {
        if (t < s) red[t] += red[t + s];
        __syncthreads();
    }
    const float inv = 1.f / red[0];
    __syncthreads();

    __half2* dst = reinterpret_cast<__half2*>(P + (size_t)ri * NN);
    for (int j = t; j < NN / 2; j += 256)
        dst[j] = __floats2half2_rn(row[2 * j] * inv, row[2 * j + 1] * inv);
}

extern "C" void kernel_launch(void* const* d_in, const int* in_sizes, int n_in,
                              void* d_out, int out_size) {
    const float* feats = (const float*)d_in[0];
    float* out = (float*)d_out;

    void *sp, *fp, *pp;
    cudaGetSymbolAddress(&sp, g_S);
    cudaGetSymbolAddress(&fp, g_Fh);
    cudaGetSymbolAddress(&pp, g_Ph);
    float* S = (float*)sp;
    __half* Fh = (__half*)fp;
    __half* Ph = (__half*)pp;

    cudaFuncSetAttribute(gemm_nt_f16, cudaFuncAttributeMaxDynamicSharedMemorySize, SMEM_TOTAL);

    prep_feats<<<(NN * NN) / 2048, 256>>>(feats, Fh);

    dim3 grid(NN / BN, NN / BM);  // (32, 32)
    // S = Fh @ Fh^T / D
    gemm_nt_f16<<<grid, THREADS, SMEM_TOTAL>>>(Fh, Fh, S, 1.0f / (float)NN);
    // P = softmax(S), diagonal masked, f16
    softmax_rows<<<NN, 256>>>(S, Ph);
    // out = P @ Fh^T / sqrt(D)
    gemm_nt_f16<<<grid, THREADS, SMEM_TOTAL>>>(Ph, Fh, out, 1.0f / 64.0f);
}

// round 7
// speedup vs baseline: 7.1910x; 1.0367x over previous
#include <cuda_runtime.h>
#include <cuda_fp16.h>
#include <stdint.h>

#define NN 4096
#define THREADS 256
#define STAGES 3
#define BK 64
#define KT (NN / BK)   // 64 iterations
#define BM 128
#define BN 128
#define LDB 144  // bytes per smem row: 64 halves (128B) + 16B pad -> conflict-free ldmatrix

#define ASTG (BM * LDB)             // 18432 bytes per operand stage
#define STG (2 * ASTG)              // 36864 per stage (A+B)
#define SMEM_TOTAL (STAGES * STG)   // 110592

// Scratch (device globals: no allocations).
__device__ __half g_Sh[(size_t)NN * NN];   // f16 logits, then probs in-place (32 MB)
__device__ __half g_Fh[(size_t)NN * NN];   // f16 feats (32 MB)

__device__ __forceinline__ uint32_t smem_u32(const void* p) {
    uint32_t a;
    asm("{ .reg .u64 t; cvta.to.shared.u64 t, %1; cvt.u32.u64 %0, t; }" : "=r"(a) : "l"(p));
    return a;
}

#define CP_ASYNC16(dst, src) \
    asm volatile("cp.async.cg.shared.global [%0], [%1], 16;" :: "r"(dst), "l"(src) : "memory")
#define CP_COMMIT() asm volatile("cp.async.commit_group;" ::: "memory")
#define CP_WAIT(n) asm volatile("cp.async.wait_group %0;" ::"n"(n) : "memory")

#define LDSM_X4(r0, r1, r2, r3, addr)                                        \
    asm volatile("ldmatrix.sync.aligned.m8n8.x4.shared.b16 {%0,%1,%2,%3}, [%4];" \
                 : "=r"(r0), "=r"(r1), "=r"(r2), "=r"(r3) : "r"(addr))

#define MMA_F16(d, a, b0, b1)                                                \
    asm volatile(                                                            \
        "mma.sync.aligned.m16n8k16.row.col.f32.f16.f16.f32 "                 \
        "{%0,%1,%2,%3}, {%4,%5,%6,%7}, {%8,%9}, {%0,%1,%2,%3};"              \
        : "+f"((d)[0]), "+f"((d)[1]), "+f"((d)[2]), "+f"((d)[3])             \
        : "r"((a)[0]), "r"((a)[1]), "r"((a)[2]), "r"((a)[3]),                \
          "r"(b0), "r"(b1))

// NT GEMM, f16 inputs, fp32 accum, OT output: C[i][j] = scale*sum_k A[i][k]*B[j][k]
template <typename OT>
__global__ __launch_bounds__(THREADS, 2) void gemm_nt_f16(const __half* __restrict__ A,
                                                          const __half* __restrict__ B,
                                                          OT* __restrict__ C, float scale) {
    extern __shared__ char smem[];
    const uint32_t sb = smem_u32(smem);
    const int tid = threadIdx.x;
    const int wid = tid >> 5;
    const int lane = tid & 31;
    const int q = lane >> 2, r = lane & 3;
    const int wm = wid & 1;   // 2 warp rows x 64
    const int wn = wid >> 1;  // 4 warp cols x 32
    const int rowBase = blockIdx.y * BM;
    const int colBase = blockIdx.x * BN;

    // cp.async: per operand tile 128 rows x 128B; thread t -> rows (t>>3)+{0,32,64,96}, chunk t&7
    const int ldRow = tid >> 3;
    const int ldC = (tid & 7) * 16;
    // running global pointers (advance 128B per issued k-tile)
    const char* Ag = (const char*)A + ((size_t)(rowBase + ldRow) * NN) * 2 + ldC;
    const char* Bg = (const char*)B + ((size_t)(colBase + ldRow) * NN) * 2 + ldC;
    const size_t GROW = (size_t)32 * NN * 2;  // 32 rows stride

    // ldmatrix lane mapping
    const int ml = lane >> 3;
    const int lrow = (ml & 1) * 8 + (lane & 7);
    const int lk = (ml >> 1) * 16;
    const uint32_t aoff = (uint32_t)((wm * 64 + lrow) * LDB + lk);
    const uint32_t boff = (uint32_t)(ASTG + (wn * 32 + lrow) * LDB + lk);

    float c[4][4][4];
#pragma unroll
    for (int i = 0; i < 4; i++)
#pragma unroll
        for (int j = 0; j < 4; j++)
#pragma unroll
            for (int e = 0; e < 4; e++) c[i][j][e] = 0.f;

#define LOADK(sidx)                                                                \
    do {                                                                           \
        const uint32_t s_b = sb + (sidx) * STG;                                    \
        _Pragma("unroll") for (int l = 0; l < 4; l++) {                            \
            CP_ASYNC16(s_b + (ldRow + l * 32) * LDB + ldC, Ag + l * GROW);         \
            CP_ASYNC16(s_b + ASTG + (ldRow + l * 32) * LDB + ldC, Bg + l * GROW);  \
        }                                                                          \
        CP_COMMIT();                                                               \
        Ag += 128;                                                                 \
        Bg += 128;                                                                 \
    } while (0)

    LOADK(0);
    LOADK(1);

    int scur = 0;   // stage being consumed
    int sld = 2;    // stage to load next

#define LOAD_FRAGS(buf, base_a, base_b, ks)                                        \
    do {                                                                           \
        _Pragma("unroll") for (int im = 0; im < 4; im++)                           \
            LDSM_X4(a[buf][im][0], a[buf][im][1], a[buf][im][2], a[buf][im][3],    \
                    (base_a) + im * (16 * LDB) + (ks) * 32);                       \
        _Pragma("unroll") for (int jn = 0; jn < 2; jn++)                           \
            LDSM_X4(b[buf][jn][0], b[buf][jn][1], b[buf][jn][2], b[buf][jn][3],    \
                    (base_b) + jn * (16 * LDB) + (ks) * 32);                       \
    } while (0)

    for (int kt = 0; kt < KT; kt++) {
        CP_WAIT(1);
        __syncthreads();  // stage (kt-1)%3 reads complete -> reusable
        if (kt + 2 < KT) {
            LOADK(sld);
            sld = (sld == STAGES - 1) ? 0 : sld + 1;
        } else {
            CP_COMMIT();
        }

        const uint32_t abase = sb + scur * STG + aoff;
        const uint32_t bbase = sb + scur * STG + boff;
        scur = (scur == STAGES - 1) ? 0 : scur + 1;

        uint32_t a[2][4][4], b[2][2][4];
        LOAD_FRAGS(0, abase, bbase, 0);
#pragma unroll
        for (int ks = 0; ks < 4; ks++) {
            const int cur = ks & 1;
            if (ks < 3) LOAD_FRAGS(cur ^ 1, abase, bbase, ks + 1);
#pragma unroll
            for (int im = 0; im < 4; im++)
#pragma unroll
                for (int in_ = 0; in_ < 4; in_++) {
                    const int jn = in_ >> 1, o = in_ & 1;
                    MMA_F16(c[im][in_], a[cur][im], b[cur][jn][o], b[cur][jn][2 + o]);
                }
        }
    }

    // epilogue
#pragma unroll
    for (int im = 0; im < 4; im++) {
        const int row0 = rowBase + wm * 64 + im * 16 + q;
#pragma unroll
        for (int in_ = 0; in_ < 4; in_++) {
            const int col = colBase + wn * 32 + in_ * 8 + 2 * r;
            if constexpr (sizeof(OT) == 4) {
                float2 v0 = make_float2(c[im][in_][0] * scale, c[im][in_][1] * scale);
                float2 v1 = make_float2(c[im][in_][2] * scale, c[im][in_][3] * scale);
                *reinterpret_cast<float2*>((float*)C + (size_t)row0 * NN + col) = v0;
                *reinterpret_cast<float2*>((float*)C + (size_t)(row0 + 8) * NN + col) = v1;
            } else {
                __half2 h0 = __floats2half2_rn(c[im][in_][0] * scale, c[im][in_][1] * scale);
                __half2 h1 = __floats2half2_rn(c[im][in_][2] * scale, c[im][in_][3] * scale);
                *reinterpret_cast<__half2*>((__half*)C + (size_t)row0 * NN + col) = h0;
                *reinterpret_cast<__half2*>((__half*)C + (size_t)(row0 + 8) * NN + col) = h1;
            }
        }
    }
}

// ---------------- prep: feats f32 -> f16 ----------------
__global__ __launch_bounds__(256) void prep_feats(const float* __restrict__ in,
                                                  __half* __restrict__ out) {
    size_t i = ((size_t)blockIdx.x * 256 + threadIdx.x) * 8;
    float4 v0 = *reinterpret_cast<const float4*>(in + i);
    float4 v1 = *reinterpret_cast<const float4*>(in + i + 4);
    __half2 h[4];
    h[0] = __floats2half2_rn(v0.x, v0.y);
    h[1] = __floats2half2_rn(v0.z, v0.w);
    h[2] = __floats2half2_rn(v1.x, v1.y);
    h[3] = __floats2half2_rn(v1.z, v1.w);
    *reinterpret_cast<uint4*>(out + i) = *reinterpret_cast<uint4*>(h);
}

// ---------------- row softmax on f16 logits, diag masked, f16 probs in-place ----------------
__global__ __launch_bounds__(256) void softmax_rows(__half* __restrict__ S) {
    __shared__ float row[NN];  // 16 KB
    __shared__ float red[256];
    const int ri = blockIdx.x;
    const int t = threadIdx.x;
    __half2* rp = reinterpret_cast<__half2*>(S + (size_t)ri * NN);

    for (int j = t; j < NN / 2; j += 256) {
        float2 v = __half22float2(rp[j]);
        row[2 * j] = v.x;
        row[2 * j + 1] = v.y;
    }
    __syncthreads();
    if (t == 0) row[ri] = -3.4e38f;  // mask diagonal
    __syncthreads();

    float m = -3.4e38f;
    for (int j = t; j < NN; j += 256) m = fmaxf(m, row[j]);
    red[t] = m;
    __syncthreads();
    for (int s = 128; s > 0; s >>= 1) {
        if (t < s) red[t] = fmaxf(red[t], red[t + s]);
        __syncthreads();
    }
    m = red[0];
    __syncthreads();

    float sum = 0.f;
    for (int j = t; j < NN; j += 256) {
        float e = __expf(row[j] - m);
        row[j] = e;
        sum += e;
    }
    red[t] = sum;
    __syncthreads();
    for (int s = 128; s > 0; s >>= 1) {
        if (t < s) red[t] += red[t + s];
        __syncthreads();
    }
    const float inv = 1.f / red[0];
    __syncthreads();

    for (int j = t; j < NN / 2; j += 256)
        rp[j] = __floats2half2_rn(row[2 * j] * inv, row[2 * j + 1] * inv);
}

extern "C" void kernel_launch(void* const* d_in, const int* in_sizes, int n_in,
                              void* d_out, int out_size) {
    const float* feats = (const float*)d_in[0];
    float* out = (float*)d_out;

    void *sp, *fp;
    cudaGetSymbolAddress(&sp, g_Sh);
    cudaGetSymbolAddress(&fp, g_Fh);
    __half* Sh = (__half*)sp;
    __half* Fh = (__half*)fp;

    cudaFuncSetAttribute(gemm_nt_f16<__half>, cudaFuncAttributeMaxDynamicSharedMemorySize,
                         SMEM_TOTAL);
    cudaFuncSetAttribute(gemm_nt_f16<float>, cudaFuncAttributeMaxDynamicSharedMemorySize,
                         SMEM_TOTAL);

    prep_feats<<<(NN * NN) / 2048, 256>>>(feats, Fh);

    dim3 grid(NN / BN, NN / BM);  // (32, 32)
    // S = Fh @ Fh^T / D  (f16 logits out)
    gemm_nt_f16<__half><<<grid, THREADS, SMEM_TOTAL>>>(Fh, Fh, Sh, 1.0f / (float)NN);
    // P = softmax(S), diag masked, in-place f16
    softmax_rows<<<NN, 256>>>(Sh);
    // out = P @ Fh^T / sqrt(D)  (fp32 out)
    gemm_nt_f16<float><<<grid, THREADS, SMEM_TOTAL>>>(Sh, Fh, out, 1.0f / 64.0f);
}